// round 5
// baseline (speedup 1.0000x reference)
#include <cuda_runtime.h>
#include <cstdint>
#include <cstdio>

// Problem dims
static constexpr int Bz  = 64;
static constexpr int Sq  = 128;
static constexpr int SRCL = 256;
static constexpr int Hd  = 512;
static constexpr int Vv  = 8000;
static constexpr int NHh = 8;
static constexpr int HDd = 64;

static constexpr int GRU_BLOCKS = 128;

// ---------------- device scratch (allocation-free rule: __device__ globals) ----
__device__ float g_qin  [(size_t)Bz * Sq * Hd];        // query_input = emb + h0
__device__ float g_q    [(size_t)Bz * Sq * Hd];
__device__ float g_k    [(size_t)Bz * SRCL * Hd];
__device__ float g_v    [(size_t)Bz * SRCL * Hd];
__device__ float g_ctx  [(size_t)Bz * Sq * Hd];
__device__ float g_gruin[(size_t)Bz * Sq * 2 * Hd];    // [emb ; attn_out]
__device__ float g_gi   [(size_t)Bz * Sq * 3 * Hd];    // precomputed input gates
__device__ float g_hbuf [2][Bz * Hd];                  // double-buffered GRU state
__device__ float g_logits[(size_t)Bz * Sq * Vv];

// grid-barrier state (monotonic across graph replays; blocks re-read base each launch)
__device__ volatile unsigned g_arr[GRU_BLOCKS];
__device__ volatile unsigned g_go;

// ---------------- embedding gather + query input + h0 init --------------------
__global__ __launch_bounds__(256)
void embed_kernel(const int* __restrict__ prev, const float* __restrict__ emb,
                  const float* __restrict__ h0) {
    int idx = blockIdx.x * 256 + threadIdx.x;
    if (idx < Bz * Sq * Hd) {
        int d = idx & (Hd - 1);
        int row = idx >> 9;          // b*Sq + s
        int b = row >> 7;
        int tok = prev[row];
        float e = emb[(size_t)tok * Hd + d];
        g_gruin[(size_t)row * (2 * Hd) + d] = e;          // first half of GRU input
        g_qin[idx] = e + h0[b * Hd + d];
    }
    if (idx < Bz * Hd) g_hbuf[0][idx] = h0[idx];
}

// ---------------- generic fp32 GEMM: C = A @ W^T + bias -----------------------
// grid = (N/64, M/64), 256 threads, 64x64 tile, BK=16, 4x4 per thread.
// All M,N multiples of 64 and K multiples of 16 in this problem (no guards).
__global__ __launch_bounds__(256)
void gemm_kernel(const float* __restrict__ A, int lda,
                 const float* __restrict__ W, int ldw,
                 const float* __restrict__ bias,
                 float* __restrict__ C, int ldc, int K) {
    __shared__ float As[64][17];
    __shared__ float Ws[64][17];
    int t = threadIdx.x;
    int tx = t & 15, ty = t >> 4;
    int m0 = blockIdx.y * 64, n0 = blockIdx.x * 64;

    float acc[4][4];
#pragma unroll
    for (int i = 0; i < 4; i++)
#pragma unroll
        for (int j = 0; j < 4; j++) acc[i][j] = 0.f;

    for (int k0 = 0; k0 < K; k0 += 16) {
#pragma unroll
        for (int i = 0; i < 4; i++) {
            int idx = t + i * 256;
            int r = idx >> 4, c = idx & 15;
            As[r][c] = A[(size_t)(m0 + r) * lda + k0 + c];
            Ws[r][c] = W[(size_t)(n0 + r) * ldw + k0 + c];
        }
        __syncthreads();
#pragma unroll
        for (int k = 0; k < 16; k++) {
            float a[4], w[4];
#pragma unroll
            for (int i = 0; i < 4; i++) a[i] = As[ty * 4 + i][k];
#pragma unroll
            for (int j = 0; j < 4; j++) w[j] = Ws[tx * 4 + j][k];
#pragma unroll
            for (int i = 0; i < 4; i++)
#pragma unroll
                for (int j = 0; j < 4; j++) acc[i][j] += a[i] * w[j];
        }
        __syncthreads();
    }
#pragma unroll
    for (int j = 0; j < 4; j++) {
        float bb = bias[n0 + tx * 4 + j];
#pragma unroll
        for (int i = 0; i < 4; i++)
            C[(size_t)(m0 + ty * 4 + i) * ldc + n0 + tx * 4 + j] = acc[i][j] + bb;
    }
}

// ---------------- attention: one block per (b, head), K/V in smem -------------
// smem: Ks[256][65] + Vs[256][65] + sc[8][256]  (floats, stride 65 -> conflict-free)
static constexpr int ATT_SMEM_FLOATS = 2 * 256 * 65 + 8 * 256;
__global__ __launch_bounds__(256)
void attn_kernel() {
    extern __shared__ float sm[];
    float* Ks = sm;
    float* Vs = sm + 256 * 65;
    float* sc = sm + 2 * 256 * 65;

    int t = threadIdx.x;
    int lane = t & 31, w = t >> 5;
    int bh = blockIdx.x;
    int b = bh >> 3, h = bh & 7;

    const float* kb = g_k + ((size_t)b * SRCL) * Hd + h * HDd;
    const float* vb = g_v + ((size_t)b * SRCL) * Hd + h * HDd;
    for (int i = t; i < 256 * 64; i += 256) {
        int l = i >> 6, d = i & 63;
        Ks[l * 65 + d] = kb[(size_t)l * Hd + d];
        Vs[l * 65 + d] = vb[(size_t)l * Hd + d];
    }
    __syncthreads();

    for (int s = w; s < Sq; s += 8) {
        const float* qr = g_q + ((size_t)(b * Sq + s)) * Hd + h * HDd;
        float qa = qr[lane], qb = qr[lane + 32];

        float acc[8];
#pragma unroll
        for (int j = 0; j < 8; j++) acc[j] = 0.f;
#pragma unroll
        for (int d = 0; d < 64; d++) {
            float qd = (d < 32) ? __shfl_sync(0xffffffffu, qa, d)
                                : __shfl_sync(0xffffffffu, qb, d - 32);
#pragma unroll
            for (int j = 0; j < 8; j++) acc[j] += qd * Ks[(j * 32 + lane) * 65 + d];
        }
        float m = -1e30f;
#pragma unroll
        for (int j = 0; j < 8; j++) { acc[j] *= 0.125f; m = fmaxf(m, acc[j]); }
#pragma unroll
        for (int off = 16; off > 0; off >>= 1)
            m = fmaxf(m, __shfl_xor_sync(0xffffffffu, m, off));

        float p[8], sum = 0.f;
#pragma unroll
        for (int j = 0; j < 8; j++) { p[j] = __expf(acc[j] - m); sum += p[j]; }
#pragma unroll
        for (int off = 16; off > 0; off >>= 1)
            sum += __shfl_xor_sync(0xffffffffu, sum, off);
        float inv = 1.f / sum;
#pragma unroll
        for (int j = 0; j < 8; j++) sc[w * 256 + j * 32 + lane] = p[j] * inv;
        __syncwarp();

        float c0 = 0.f, c1 = 0.f;
#pragma unroll 8
        for (int l = 0; l < 256; l++) {
            float pl = sc[w * 256 + l];
            c0 += pl * Vs[l * 65 + lane];
            c1 += pl * Vs[l * 65 + lane + 32];
        }
        float* cr = g_ctx + ((size_t)(b * Sq + s)) * Hd + h * HDd;
        cr[lane] = c0;
        cr[lane + 32] = c1;
    }
}

// ---------------- persistent GRU scan ----------------------------------------
// 128 blocks x 256 threads, all resident (<= 148 SMs). Block bid owns j-slice
// {bid*4 .. bid*4+3} across all 3 gates; thread t -> (b = t&63, jj = t>>6).
// One grid barrier per step; h double-buffered; h read via __ldcg (L2).
__device__ __forceinline__ void grid_barrier(unsigned target) {
    __threadfence();
    __syncthreads();
    if (threadIdx.x == 0) g_arr[blockIdx.x] = target;
    if (blockIdx.x == 0) {
        for (int j = threadIdx.x; j < GRU_BLOCKS; j += blockDim.x)
            while (g_arr[j] < target) {}
        __syncthreads();
        if (threadIdx.x == 0) { __threadfence(); g_go = target; }
    }
    if (threadIdx.x == 0) { while (g_go < target) {} }
    __syncthreads();
}

__global__ __launch_bounds__(256)
void gru_kernel(const float* __restrict__ w_hh, const float* __restrict__ b_hh,
                float* __restrict__ hs_out) {
    __shared__ float h_s[64][36];
    __shared__ float w_s[12][36];
    __shared__ unsigned s_base;

    int t = threadIdx.x;
    if (t == 0) s_base = g_arr[blockIdx.x];
    __syncthreads();
    unsigned base = s_base;

    const int b = t & 63;
    const int jj = t >> 6;
    const int j0 = blockIdx.x * 4;
    const int j = j0 + jj;

    const float bhr = b_hh[j];
    const float bhz = b_hh[512 + j];
    const float bhn = b_hh[1024 + j];

    for (int s = 0; s < Sq; s++) {
        const float* hin = g_hbuf[s & 1];
        float acc0 = 0.f, acc1 = 0.f, acc2 = 0.f;

        for (int k0 = 0; k0 < Hd; k0 += 32) {
            __syncthreads();
#pragma unroll
            for (int i = 0; i < 8; i++) {
                int idx = t + i * 256;
                int r = idx >> 5, c = idx & 31;
                h_s[r][c] = __ldcg(&hin[r * Hd + k0 + c]);
            }
            for (int i = t; i < 384; i += 256) {
                int r = i >> 5, c = i & 31;
                int n = j0 + (r & 3) + 512 * (r >> 2);
                w_s[r][c] = w_hh[(size_t)n * Hd + k0 + c];
            }
            __syncthreads();
#pragma unroll
            for (int kk = 0; kk < 8; kk++) {
                float4 hv = *reinterpret_cast<const float4*>(&h_s[b][kk * 4]);
                float4 w0 = *reinterpret_cast<const float4*>(&w_s[jj][kk * 4]);
                float4 w1 = *reinterpret_cast<const float4*>(&w_s[4 + jj][kk * 4]);
                float4 w2 = *reinterpret_cast<const float4*>(&w_s[8 + jj][kk * 4]);
                acc0 += hv.x * w0.x; acc0 += hv.y * w0.y; acc0 += hv.z * w0.z; acc0 += hv.w * w0.w;
                acc1 += hv.x * w1.x; acc1 += hv.y * w1.y; acc1 += hv.z * w1.z; acc1 += hv.w * w1.w;
                acc2 += hv.x * w2.x; acc2 += hv.y * w2.y; acc2 += hv.z * w2.z; acc2 += hv.w * w2.w;
            }
        }

        const float* gi = g_gi + ((size_t)(b * Sq + s)) * (3 * Hd);
        float ir = gi[j], iz = gi[512 + j], inn = gi[1024 + j];
        float r = 1.f / (1.f + __expf(-(ir + acc0 + bhr)));
        float z = 1.f / (1.f + __expf(-(iz + acc1 + bhz)));
        float n = tanhf(inn + r * (acc2 + bhn));
        float hprev = __ldcg(&hin[b * Hd + j]);
        float hnew = (1.f - z) * n + z * hprev;

        g_hbuf[(s + 1) & 1][b * Hd + j] = hnew;
        hs_out[((size_t)(b * Sq + s)) * Hd + j] = hnew;

        if (s < Sq - 1) grid_barrier(base + (unsigned)s + 1u);
    }
}

// ---------------- row softmax over V=8000 -------------------------------------
__global__ __launch_bounds__(256)
void softmax_kernel(const float* __restrict__ x, float* __restrict__ y) {
    __shared__ float srow[Vv];
    __shared__ float red[8];
    __shared__ float s_b;
    int t = threadIdx.x;
    size_t row = blockIdx.x;
    const float* xr = x + row * Vv;

    float m = -1e30f;
    for (int i = t; i < Vv; i += 256) { float v = xr[i]; srow[i] = v; m = fmaxf(m, v); }
#pragma unroll
    for (int off = 16; off > 0; off >>= 1) m = fmaxf(m, __shfl_xor_sync(0xffffffffu, m, off));
    if ((t & 31) == 0) red[t >> 5] = m;
    __syncthreads();
    if (t == 0) {
        float mm = red[0];
#pragma unroll
        for (int i = 1; i < 8; i++) mm = fmaxf(mm, red[i]);
        s_b = mm;
    }
    __syncthreads();
    m = s_b;

    float sum = 0.f;
    for (int i = t; i < Vv; i += 256) { float e = __expf(srow[i] - m); srow[i] = e; sum += e; }
#pragma unroll
    for (int off = 16; off > 0; off >>= 1) sum += __shfl_xor_sync(0xffffffffu, sum, off);
    if ((t & 31) == 0) red[t >> 5] = sum;
    __syncthreads();
    if (t == 0) {
        float ss = 0.f;
#pragma unroll
        for (int i = 0; i < 8; i++) ss += red[i];
        s_b = 1.f / ss;
    }
    __syncthreads();
    float inv = s_b;
    float* yr = y + row * Vv;
    for (int i = t; i < Vv; i += 256) yr[i] = srow[i] * inv;
}

// ---------------- launch ------------------------------------------------------
extern "C" void kernel_launch(void* const* d_in, const int* in_sizes, int n_in,
                              void* d_out, int out_size) {
    const float* enc  = (const float*)d_in[0];
    const int*   prev = (const int*)d_in[1];
    const float* h0   = (const float*)d_in[2];
    const float* emb  = (const float*)d_in[3];
    const float* inw  = (const float*)d_in[4];
    const float* inb  = (const float*)d_in[5];
    const float* ow   = (const float*)d_in[6];
    const float* ob   = (const float*)d_in[7];
    const float* wih  = (const float*)d_in[8];
    const float* whh  = (const float*)d_in[9];
    const float* bih  = (const float*)d_in[10];
    const float* bhh  = (const float*)d_in[11];
    const float* pw   = (const float*)d_in[12];
    const float* pb   = (const float*)d_in[13];

    float* probs = (float*)d_out;
    float* hs    = probs + (size_t)Bz * Sq * Vv;

    float *qin, *q, *k, *v, *ctx, *gruin, *gi, *logits;
    cudaGetSymbolAddress((void**)&qin,    g_qin);
    cudaGetSymbolAddress((void**)&q,      g_q);
    cudaGetSymbolAddress((void**)&k,      g_k);
    cudaGetSymbolAddress((void**)&v,      g_v);
    cudaGetSymbolAddress((void**)&ctx,    g_ctx);
    cudaGetSymbolAddress((void**)&gruin,  g_gruin);
    cudaGetSymbolAddress((void**)&gi,     g_gi);
    cudaGetSymbolAddress((void**)&logits, g_logits);

    cudaFuncSetAttribute(attn_kernel, cudaFuncAttributeMaxDynamicSharedMemorySize,
                         ATT_SMEM_FLOATS * (int)sizeof(float));

    // 1. embedding gather + query input + h0 init
    embed_kernel<<<(Bz * Sq * Hd + 255) / 256, 256>>>(prev, emb, h0);

    // 2. q/k/v projections
    gemm_kernel<<<dim3(Hd / 64, (Bz * Sq) / 64), 256>>>(qin, Hd, inw, Hd, inb, q, Hd, Hd);
    gemm_kernel<<<dim3(Hd / 64, (Bz * SRCL) / 64), 256>>>(enc, Hd, inw + (size_t)512 * 512, Hd,
                                                          inb + 512, k, Hd, Hd);
    gemm_kernel<<<dim3(Hd / 64, (Bz * SRCL) / 64), 256>>>(enc, Hd, inw + (size_t)1024 * 512, Hd,
                                                          inb + 1024, v, Hd, Hd);
    // 3. attention
    attn_kernel<<<Bz * NHh, 256, ATT_SMEM_FLOATS * (int)sizeof(float)>>>();

    // 4. out projection, written into second half of gru input (ldc = 2H)
    gemm_kernel<<<dim3(Hd / 64, (Bz * Sq) / 64), 256>>>(ctx, Hd, ow, Hd, ob,
                                                        gruin + Hd, 2 * Hd, Hd);
    // 5. input-gate precompute gi = gru_input @ w_ih^T + b_ih
    gemm_kernel<<<dim3((3 * Hd) / 64, (Bz * Sq) / 64), 256>>>(gruin, 2 * Hd, wih, 2 * Hd, bih,
                                                              gi, 3 * Hd, 2 * Hd);
    // 6. recurrent scan (persistent)
    gru_kernel<<<GRU_BLOCKS, 256>>>(whh, bhh, hs);

    // 7. vocab projection + softmax
    gemm_kernel<<<dim3(Vv / 64, (Bz * Sq) / 64), 256>>>(hs, Hd, pw, Hd, pb, logits, Vv, Hd);
    softmax_kernel<<<Bz * Sq, 256>>>(logits, probs);
}

// round 16
// speedup vs baseline: 1.6668x; 1.6668x over previous
#include <cuda_runtime.h>
#include <cuda_bf16.h>
#include <cstdint>
#include <cstdio>

// Problem dims
static constexpr int Bz  = 64;
static constexpr int Sq  = 128;
static constexpr int SRCL = 256;
static constexpr int Hd  = 512;
static constexpr int Vv  = 8000;
static constexpr int NHh = 8;
static constexpr int HDd = 64;
static constexpr int Vpad = 8064;           // 63 * 128

static constexpr int GRU_BLOCKS = 128;

// ---------------- device scratch (allocation-free rule: __device__ globals) ----
__device__ float g_qin  [(size_t)Bz * Sq * Hd];
__device__ float g_q    [(size_t)Bz * Sq * Hd];
__device__ float g_k    [(size_t)Bz * SRCL * Hd];
__device__ float g_v    [(size_t)Bz * SRCL * Hd];
__device__ float g_ctx  [(size_t)Bz * Sq * Hd];
__device__ float g_gruin[(size_t)Bz * Sq * 2 * Hd];
__device__ float g_gi   [(size_t)Bz * Sq * 3 * Hd];
__device__ float g_hbuf [2][Bz * Hd];
__device__ float g_logits[(size_t)Bz * Sq * Vv];

// bf16 hi/lo split operands for tensor-core GEMMs
__device__ __nv_bfloat16 g_qin_h[(size_t)Bz*Sq*Hd],   g_qin_l[(size_t)Bz*Sq*Hd];
__device__ __nv_bfloat16 g_enc_h[(size_t)Bz*SRCL*Hd], g_enc_l[(size_t)Bz*SRCL*Hd];
__device__ __nv_bfloat16 g_ctx_h[(size_t)Bz*Sq*Hd],   g_ctx_l[(size_t)Bz*Sq*Hd];
__device__ __nv_bfloat16 g_gin_h[(size_t)Bz*Sq*2*Hd], g_gin_l[(size_t)Bz*Sq*2*Hd];
__device__ __nv_bfloat16 g_hs_h [(size_t)Bz*Sq*Hd],   g_hs_l [(size_t)Bz*Sq*Hd];
__device__ __nv_bfloat16 g_inw_h[(size_t)3*Hd*Hd],    g_inw_l[(size_t)3*Hd*Hd];
__device__ __nv_bfloat16 g_ow_h [(size_t)Hd*Hd],      g_ow_l [(size_t)Hd*Hd];
__device__ __nv_bfloat16 g_wih_h[(size_t)3*Hd*2*Hd],  g_wih_l[(size_t)3*Hd*2*Hd];
__device__ __nv_bfloat16 g_pw_h [(size_t)Vpad*Hd],    g_pw_l [(size_t)Vpad*Hd];

// grid-barrier state (monotonic across graph replays)
__device__ volatile unsigned g_arr[GRU_BLOCKS];
__device__ volatile unsigned g_go;

// ======================= helpers ==============================================
__device__ __forceinline__ uint32_t smem_u32(const void* p) {
    uint32_t a;
    asm("{ .reg .u64 t; cvta.to.shared.u64 t, %1; cvt.u32.u64 %0, t; }" : "=r"(a) : "l"(p));
    return a;
}
#define CP_ASYNC16(saddr, gptr) \
    asm volatile("cp.async.ca.shared.global [%0], [%1], 16;" \
                 :: "r"(saddr), "l"(gptr) : "memory")
#define CP_COMMIT() asm volatile("cp.async.commit_group;" ::: "memory")
#define CP_WAIT(n)  asm volatile("cp.async.wait_group %0;" :: "n"(n) : "memory")

__device__ __forceinline__ void mma_bf16(float* c, const uint32_t* a, const uint32_t* b) {
    asm volatile(
        "mma.sync.aligned.m16n8k16.row.col.f32.bf16.bf16.f32 "
        "{%0,%1,%2,%3}, {%4,%5,%6,%7}, {%8,%9}, {%0,%1,%2,%3};"
        : "+f"(c[0]), "+f"(c[1]), "+f"(c[2]), "+f"(c[3])
        : "r"(a[0]), "r"(a[1]), "r"(a[2]), "r"(a[3]), "r"(b[0]), "r"(b[1]));
}

// ======================= fp32 -> bf16 hi/lo split =============================
__global__ __launch_bounds__(256)
void cvt_kernel(const float* __restrict__ src, __nv_bfloat16* __restrict__ hi,
                __nv_bfloat16* __restrict__ lo, long nvalid, long ntot) {
    long i = ((long)blockIdx.x * 256 + threadIdx.x) * 4;
    if (i >= ntot) return;
    float4 v = make_float4(0.f, 0.f, 0.f, 0.f);
    if (i < nvalid) v = *reinterpret_cast<const float4*>(src + i);
    __nv_bfloat16 h[4], l[4];
    float f[4] = {v.x, v.y, v.z, v.w};
#pragma unroll
    for (int j = 0; j < 4; j++) {
        h[j] = __float2bfloat16(f[j]);
        l[j] = __float2bfloat16(f[j] - __bfloat162float(h[j]));
    }
    *reinterpret_cast<__nv_bfloat162*>(hi + i)     = __nv_bfloat162(h[0], h[1]);
    *reinterpret_cast<__nv_bfloat162*>(hi + i + 2) = __nv_bfloat162(h[2], h[3]);
    *reinterpret_cast<__nv_bfloat162*>(lo + i)     = __nv_bfloat162(l[0], l[1]);
    *reinterpret_cast<__nv_bfloat162*>(lo + i + 2) = __nv_bfloat162(l[2], l[3]);
}

// ======================= mma.sync split GEMM ==================================
// C[M x Nreal] = A[M x K] @ W[N x K]^T + bias, via Ah*Wh + Ah*Wl + Al*Wh.
// CTA tile 128x128, 8 warps (4 M x 2 N), warp tile 32x64. K-chunk 32.
// Smem: 4 arrays (Ah,Al,Wh,Wl) of 128 rows x 16 uint32 (bf16 pairs), row
// stride 20 uint32 (80B, 16B-aligned, conflict-free). Double buffered (cp.async).
static constexpr int ST = 20;                   // uint32 row stride
static constexpr int ARR = 128 * ST;            // 2560 uint32 per array
static constexpr int STAGE_U32 = 4 * ARR;       // 10240 uint32 per stage
static constexpr int MM_SMEM = 2 * STAGE_U32 * 4;   // 81920 bytes

__global__ __launch_bounds__(256)
void mm_gemm(const __nv_bfloat16* __restrict__ Ah, const __nv_bfloat16* __restrict__ Al,
             const __nv_bfloat16* __restrict__ Wh, const __nv_bfloat16* __restrict__ Wl,
             const float* __restrict__ bias, float* __restrict__ C,
             int K, int ldc, int Nreal) {
    extern __shared__ uint32_t smp[];
    const int t = threadIdx.x;
    const int lane = t & 31, wid = t >> 5;
    const int wm = wid >> 1, wn = wid & 1;
    const int m0 = blockIdx.y * 128;
    const int n0 = blockIdx.x * 128;
    const uint32_t sbase = smem_u32(smp);

    float acc[2][8][4];
#pragma unroll
    for (int mt = 0; mt < 2; mt++)
#pragma unroll
        for (int nt = 0; nt < 8; nt++)
#pragma unroll
            for (int j = 0; j < 4; j++) acc[mt][nt][j] = 0.f;

    const int nch = K >> 5;

    // ---- async load of chunk c into stage c&1 ----
    const int uid0 = t * 2;
#define ISSUE_LOAD(c) do { \
    const int st_ = (c) & 1; \
    const uint32_t sb_ = sbase + (uint32_t)(st_ * STAGE_U32 * 4); \
    const int k0_ = (c) << 5; \
    _Pragma("unroll") \
    for (int i_ = 0; i_ < 2; ++i_) { \
        int uid_ = uid0 + i_; \
        int r_ = uid_ >> 2, c4_ = uid_ & 3; \
        uint32_t so_ = (uint32_t)((r_ * ST + c4_ * 4) * 4); \
        size_t gA_ = (size_t)(m0 + r_) * K + k0_ + c4_ * 8; \
        size_t gW_ = (size_t)(n0 + r_) * K + k0_ + c4_ * 8; \
        CP_ASYNC16(sb_ + so_,               Ah + gA_); \
        CP_ASYNC16(sb_ + ARR * 4 + so_,     Al + gA_); \
        CP_ASYNC16(sb_ + 2 * ARR * 4 + so_, Wh + gW_); \
        CP_ASYNC16(sb_ + 3 * ARR * 4 + so_, Wl + gW_); \
    } \
    CP_COMMIT(); \
} while (0)

    ISSUE_LOAD(0);
    const int r = lane >> 2;
    const int kc = lane & 3;

    for (int c = 0; c < nch; ++c) {
        if (c + 1 < nch) { ISSUE_LOAD(c + 1); CP_WAIT(1); }
        else             { CP_WAIT(0); }
        __syncthreads();

        const uint32_t* sg  = smp + (c & 1) * STAGE_U32;
        const uint32_t* sAh = sg;
        const uint32_t* sAl = sg + ARR;
        const uint32_t* sWh = sg + 2 * ARR;
        const uint32_t* sWl = sg + 3 * ARR;

#pragma unroll
        for (int ks = 0; ks < 2; ++ks) {
            uint32_t aH[2][4], aL[2][4];
#pragma unroll
            for (int mt = 0; mt < 2; ++mt) {
                int row = wm * 32 + mt * 16 + r;
                const uint32_t* ph = sAh + row * ST + ks * 8 + kc;
                const uint32_t* pl = sAl + row * ST + ks * 8 + kc;
                aH[mt][0] = ph[0];       aH[mt][1] = ph[8 * ST];
                aH[mt][2] = ph[4];       aH[mt][3] = ph[8 * ST + 4];
                aL[mt][0] = pl[0];       aL[mt][1] = pl[8 * ST];
                aL[mt][2] = pl[4];       aL[mt][3] = pl[8 * ST + 4];
            }
#pragma unroll
            for (int nt = 0; nt < 8; ++nt) {
                int nrow = wn * 64 + nt * 8 + r;
                const uint32_t* qh = sWh + nrow * ST + ks * 8 + kc;
                const uint32_t* ql = sWl + nrow * ST + ks * 8 + kc;
                uint32_t bH[2] = { qh[0], qh[4] };
                uint32_t bL[2] = { ql[0], ql[4] };
#pragma unroll
                for (int mt = 0; mt < 2; ++mt) {
                    mma_bf16(acc[mt][nt], aH[mt], bH);
                    mma_bf16(acc[mt][nt], aH[mt], bL);
                    mma_bf16(acc[mt][nt], aL[mt], bH);
                }
            }
        }
        __syncthreads();
    }
#undef ISSUE_LOAD

    // epilogue
#pragma unroll
    for (int mt = 0; mt < 2; ++mt) {
        int row0 = m0 + wm * 32 + mt * 16 + r;
#pragma unroll
        for (int nt = 0; nt < 8; ++nt) {
            int col = n0 + wn * 64 + nt * 8 + kc * 2;
            if (col < Nreal) {
                float b0 = bias[col], b1 = bias[col + 1];
                float2 v0 = make_float2(acc[mt][nt][0] + b0, acc[mt][nt][1] + b1);
                float2 v1 = make_float2(acc[mt][nt][2] + b0, acc[mt][nt][3] + b1);
                *reinterpret_cast<float2*>(C + (size_t)row0 * ldc + col) = v0;
                *reinterpret_cast<float2*>(C + (size_t)(row0 + 8) * ldc + col) = v1;
            }
        }
    }
}

// ---------------- embedding gather + query input + h0 init --------------------
__global__ __launch_bounds__(256)
void embed_kernel(const int* __restrict__ prev, const float* __restrict__ emb,
                  const float* __restrict__ h0) {
    int idx = blockIdx.x * 256 + threadIdx.x;
    if (idx < Bz * Sq * Hd) {
        int d = idx & (Hd - 1);
        int row = idx >> 9;
        int b = row >> 7;
        int tok = prev[row];
        float e = emb[(size_t)tok * Hd + d];
        g_gruin[(size_t)row * (2 * Hd) + d] = e;
        g_qin[idx] = e + h0[b * Hd + d];
    }
    if (idx < Bz * Hd) g_hbuf[0][idx] = h0[idx];
}

// ---------------- attention (unchanged) ---------------------------------------
static constexpr int ATT_SMEM_FLOATS = 2 * 256 * 65 + 8 * 256;
__global__ __launch_bounds__(256)
void attn_kernel() {
    extern __shared__ float smf[];
    float* Ks = smf;
    float* Vs = smf + 256 * 65;
    float* sc = smf + 2 * 256 * 65;

    int t = threadIdx.x;
    int lane = t & 31, w = t >> 5;
    int bh = blockIdx.x;
    int b = bh >> 3, h = bh & 7;

    const float* kb = g_k + ((size_t)b * SRCL) * Hd + h * HDd;
    const float* vb = g_v + ((size_t)b * SRCL) * Hd + h * HDd;
    for (int i = t; i < 256 * 64; i += 256) {
        int l = i >> 6, d = i & 63;
        Ks[l * 65 + d] = kb[(size_t)l * Hd + d];
        Vs[l * 65 + d] = vb[(size_t)l * Hd + d];
    }
    __syncthreads();

    for (int s = w; s < Sq; s += 8) {
        const float* qr = g_q + ((size_t)(b * Sq + s)) * Hd + h * HDd;
        float qa = qr[lane], qb = qr[lane + 32];

        float acc[8];
#pragma unroll
        for (int j = 0; j < 8; j++) acc[j] = 0.f;
#pragma unroll
        for (int d = 0; d < 64; d++) {
            float qd = (d < 32) ? __shfl_sync(0xffffffffu, qa, d)
                                : __shfl_sync(0xffffffffu, qb, d - 32);
#pragma unroll
            for (int j = 0; j < 8; j++) acc[j] += qd * Ks[(j * 32 + lane) * 65 + d];
        }
        float m = -1e30f;
#pragma unroll
        for (int j = 0; j < 8; j++) { acc[j] *= 0.125f; m = fmaxf(m, acc[j]); }
#pragma unroll
        for (int off = 16; off > 0; off >>= 1)
            m = fmaxf(m, __shfl_xor_sync(0xffffffffu, m, off));

        float p[8], sum = 0.f;
#pragma unroll
        for (int j = 0; j < 8; j++) { p[j] = __expf(acc[j] - m); sum += p[j]; }
#pragma unroll
        for (int off = 16; off > 0; off >>= 1)
            sum += __shfl_xor_sync(0xffffffffu, sum, off);
        float inv = 1.f / sum;
#pragma unroll
        for (int j = 0; j < 8; j++) sc[w * 256 + j * 32 + lane] = p[j] * inv;
        __syncwarp();

        float c0 = 0.f, c1 = 0.f;
#pragma unroll 8
        for (int l = 0; l < 256; l++) {
            float pl = sc[w * 256 + l];
            c0 += pl * Vs[l * 65 + lane];
            c1 += pl * Vs[l * 65 + lane + 32];
        }
        float* cr = g_ctx + ((size_t)(b * Sq + s)) * Hd + h * HDd;
        cr[lane] = c0;
        cr[lane + 32] = c1;
    }
}

// ---------------- persistent GRU scan (unchanged) ------------------------------
__device__ __forceinline__ void grid_barrier(unsigned target) {
    __threadfence();
    __syncthreads();
    if (threadIdx.x == 0) g_arr[blockIdx.x] = target;
    if (blockIdx.x == 0) {
        for (int j = threadIdx.x; j < GRU_BLOCKS; j += blockDim.x)
            while (g_arr[j] < target) {}
        __syncthreads();
        if (threadIdx.x == 0) { __threadfence(); g_go = target; }
    }
    if (threadIdx.x == 0) { while (g_go < target) {} }
    __syncthreads();
}

__global__ __launch_bounds__(256)
void gru_kernel(const float* __restrict__ w_hh, const float* __restrict__ b_hh,
                float* __restrict__ hs_out) {
    __shared__ float h_s[64][36];
    __shared__ float w_s[12][36];
    __shared__ unsigned s_base;

    int t = threadIdx.x;
    if (t == 0) s_base = g_arr[blockIdx.x];
    __syncthreads();
    unsigned base = s_base;

    const int b = t & 63;
    const int jj = t >> 6;
    const int j0 = blockIdx.x * 4;
    const int j = j0 + jj;

    const float bhr = b_hh[j];
    const float bhz = b_hh[512 + j];
    const float bhn = b_hh[1024 + j];

    for (int s = 0; s < Sq; s++) {
        const float* hin = g_hbuf[s & 1];
        float acc0 = 0.f, acc1 = 0.f, acc2 = 0.f;

        for (int k0 = 0; k0 < Hd; k0 += 32) {
            __syncthreads();
#pragma unroll
            for (int i = 0; i < 8; i++) {
                int idx = t + i * 256;
                int r = idx >> 5, c = idx & 31;
                h_s[r][c] = __ldcg(&hin[r * Hd + k0 + c]);
            }
            for (int i = t; i < 384; i += 256) {
                int r = i >> 5, c = i & 31;
                int n = j0 + (r & 3) + 512 * (r >> 2);
                w_s[r][c] = w_hh[(size_t)n * Hd + k0 + c];
            }
            __syncthreads();
#pragma unroll
            for (int kk = 0; kk < 8; kk++) {
                float4 hv = *reinterpret_cast<const float4*>(&h_s[b][kk * 4]);
                float4 w0 = *reinterpret_cast<const float4*>(&w_s[jj][kk * 4]);
                float4 w1 = *reinterpret_cast<const float4*>(&w_s[4 + jj][kk * 4]);
                float4 w2 = *reinterpret_cast<const float4*>(&w_s[8 + jj][kk * 4]);
                acc0 += hv.x * w0.x; acc0 += hv.y * w0.y; acc0 += hv.z * w0.z; acc0 += hv.w * w0.w;
                acc1 += hv.x * w1.x; acc1 += hv.y * w1.y; acc1 += hv.z * w1.z; acc1 += hv.w * w1.w;
                acc2 += hv.x * w2.x; acc2 += hv.y * w2.y; acc2 += hv.z * w2.z; acc2 += hv.w * w2.w;
            }
        }

        const float* gi = g_gi + ((size_t)(b * Sq + s)) * (3 * Hd);
        float ir = gi[j], iz = gi[512 + j], inn = gi[1024 + j];
        float r = 1.f / (1.f + __expf(-(ir + acc0 + bhr)));
        float z = 1.f / (1.f + __expf(-(iz + acc1 + bhz)));
        float n = tanhf(inn + r * (acc2 + bhn));
        float hprev = __ldcg(&hin[b * Hd + j]);
        float hnew = (1.f - z) * n + z * hprev;

        g_hbuf[(s + 1) & 1][b * Hd + j] = hnew;
        hs_out[((size_t)(b * Sq + s)) * Hd + j] = hnew;

        if (s < Sq - 1) grid_barrier(base + (unsigned)s + 1u);
    }
}

// ---------------- row softmax over V=8000 (unchanged) --------------------------
__global__ __launch_bounds__(256)
void softmax_kernel(const float* __restrict__ x, float* __restrict__ y) {
    __shared__ float srow[Vv];
    __shared__ float red[8];
    __shared__ float s_b;
    int t = threadIdx.x;
    size_t row = blockIdx.x;
    const float* xr = x + row * Vv;

    float m = -1e30f;
    for (int i = t; i < Vv; i += 256) { float v = xr[i]; srow[i] = v; m = fmaxf(m, v); }
#pragma unroll
    for (int off = 16; off > 0; off >>= 1) m = fmaxf(m, __shfl_xor_sync(0xffffffffu, m, off));
    if ((t & 31) == 0) red[t >> 5] = m;
    __syncthreads();
    if (t == 0) {
        float mm = red[0];
#pragma unroll
        for (int i = 1; i < 8; i++) mm = fmaxf(mm, red[i]);
        s_b = mm;
    }
    __syncthreads();
    m = s_b;

    float sum = 0.f;
    for (int i = t; i < Vv; i += 256) { float e = __expf(srow[i] - m); srow[i] = e; sum += e; }
#pragma unroll
    for (int off = 16; off > 0; off >>= 1) sum += __shfl_xor_sync(0xffffffffu, sum, off);
    if ((t & 31) == 0) red[t >> 5] = sum;
    __syncthreads();
    if (t == 0) {
        float ss = 0.f;
#pragma unroll
        for (int i = 0; i < 8; i++) ss += red[i];
        s_b = 1.f / ss;
    }
    __syncthreads();
    float inv = s_b;
    float* yr = y + row * Vv;
    for (int i = t; i < Vv; i += 256) yr[i] = srow[i] * inv;
}

// ---------------- launch ------------------------------------------------------
static inline void cvt(const float* src, __nv_bfloat16* hi, __nv_bfloat16* lo,
                       long nvalid, long ntot) {
    long q = ntot / 4;
    int grid = (int)((q + 255) / 256);
    cvt_kernel<<<grid, 256>>>(src, hi, lo, nvalid, ntot);
}

extern "C" void kernel_launch(void* const* d_in, const int* in_sizes, int n_in,
                              void* d_out, int out_size) {
    const float* enc  = (const float*)d_in[0];
    const int*   prev = (const int*)d_in[1];
    const float* h0   = (const float*)d_in[2];
    const float* emb  = (const float*)d_in[3];
    const float* inw  = (const float*)d_in[4];
    const float* inb  = (const float*)d_in[5];
    const float* ow   = (const float*)d_in[6];
    const float* ob   = (const float*)d_in[7];
    const float* wih  = (const float*)d_in[8];
    const float* whh  = (const float*)d_in[9];
    const float* bih  = (const float*)d_in[10];
    const float* bhh  = (const float*)d_in[11];
    const float* pw   = (const float*)d_in[12];
    const float* pb   = (const float*)d_in[13];

    float* probs = (float*)d_out;
    float* hs    = probs + (size_t)Bz * Sq * Vv;

    float *qin, *q, *k, *v, *ctx, *gruin, *gi, *logits;
    cudaGetSymbolAddress((void**)&qin,    g_qin);
    cudaGetSymbolAddress((void**)&q,      g_q);
    cudaGetSymbolAddress((void**)&k,      g_k);
    cudaGetSymbolAddress((void**)&v,      g_v);
    cudaGetSymbolAddress((void**)&ctx,    g_ctx);
    cudaGetSymbolAddress((void**)&gruin,  g_gruin);
    cudaGetSymbolAddress((void**)&gi,     g_gi);
    cudaGetSymbolAddress((void**)&logits, g_logits);

    __nv_bfloat16 *qin_h, *qin_l, *enc_h, *enc_l, *ctx_h, *ctx_l, *gin_h, *gin_l;
    __nv_bfloat16 *hs_h, *hs_l, *inw_h, *inw_l, *ow_h, *ow_l, *wih_h, *wih_l, *pw_h, *pw_l;
    cudaGetSymbolAddress((void**)&qin_h, g_qin_h); cudaGetSymbolAddress((void**)&qin_l, g_qin_l);
    cudaGetSymbolAddress((void**)&enc_h, g_enc_h); cudaGetSymbolAddress((void**)&enc_l, g_enc_l);
    cudaGetSymbolAddress((void**)&ctx_h, g_ctx_h); cudaGetSymbolAddress((void**)&ctx_l, g_ctx_l);
    cudaGetSymbolAddress((void**)&gin_h, g_gin_h); cudaGetSymbolAddress((void**)&gin_l, g_gin_l);
    cudaGetSymbolAddress((void**)&hs_h,  g_hs_h);  cudaGetSymbolAddress((void**)&hs_l,  g_hs_l);
    cudaGetSymbolAddress((void**)&inw_h, g_inw_h); cudaGetSymbolAddress((void**)&inw_l, g_inw_l);
    cudaGetSymbolAddress((void**)&ow_h,  g_ow_h);  cudaGetSymbolAddress((void**)&ow_l,  g_ow_l);
    cudaGetSymbolAddress((void**)&wih_h, g_wih_h); cudaGetSymbolAddress((void**)&wih_l, g_wih_l);
    cudaGetSymbolAddress((void**)&pw_h,  g_pw_h);  cudaGetSymbolAddress((void**)&pw_l,  g_pw_l);

    cudaFuncSetAttribute(attn_kernel, cudaFuncAttributeMaxDynamicSharedMemorySize,
                         ATT_SMEM_FLOATS * (int)sizeof(float));
    cudaFuncSetAttribute(mm_gemm, cudaFuncAttributeMaxDynamicSharedMemorySize, MM_SMEM);

    const int MR = Bz * Sq;           // 8192 rows
    const int MK = Bz * SRCL;         // 16384 rows

    // 1. embedding gather + query input + h0 init
    embed_kernel<<<(Bz * Sq * Hd + 255) / 256, 256>>>(prev, emb, h0);

    // 2. weight + activation hi/lo conversions
    cvt(inw, inw_h, inw_l, (long)3 * Hd * Hd, (long)3 * Hd * Hd);
    cvt(ow,  ow_h,  ow_l,  (long)Hd * Hd,     (long)Hd * Hd);
    cvt(wih, wih_h, wih_l, (long)3 * Hd * 2 * Hd, (long)3 * Hd * 2 * Hd);
    cvt(pw,  pw_h,  pw_l,  (long)Vv * Hd,     (long)Vpad * Hd);     // zero-padded rows
    cvt(enc, enc_h, enc_l, (long)MK * Hd,     (long)MK * Hd);
    cvt(qin, qin_h, qin_l, (long)MR * Hd,     (long)MR * Hd);

    // 3. q/k/v projections (tensor cores via mma.sync)
    mm_gemm<<<dim3(Hd / 128, MR / 128), 256, MM_SMEM>>>(qin_h, qin_l, inw_h, inw_l,
                                                        inb, q, Hd, Hd, Hd);
    mm_gemm<<<dim3(Hd / 128, MK / 128), 256, MM_SMEM>>>(enc_h, enc_l,
                                                        inw_h + (size_t)512 * 512,
                                                        inw_l + (size_t)512 * 512,
                                                        inb + 512, k, Hd, Hd, Hd);
    mm_gemm<<<dim3(Hd / 128, MK / 128), 256, MM_SMEM>>>(enc_h, enc_l,
                                                        inw_h + (size_t)1024 * 512,
                                                        inw_l + (size_t)1024 * 512,
                                                        inb + 1024, v, Hd, Hd, Hd);
    // 4. attention
    attn_kernel<<<Bz * NHh, 256, ATT_SMEM_FLOATS * (int)sizeof(float)>>>();

    // 5. out projection into second half of gru input (ldc = 2H)
    cvt(ctx, ctx_h, ctx_l, (long)MR * Hd, (long)MR * Hd);
    mm_gemm<<<dim3(Hd / 128, MR / 128), 256, MM_SMEM>>>(ctx_h, ctx_l, ow_h, ow_l,
                                                        ob, gruin + Hd, Hd, 2 * Hd, Hd);
    // 6. gi = gru_input @ w_ih^T + b_ih
    cvt(gruin, gin_h, gin_l, (long)MR * 2 * Hd, (long)MR * 2 * Hd);
    mm_gemm<<<dim3((3 * Hd) / 128, MR / 128), 256, MM_SMEM>>>(gin_h, gin_l, wih_h, wih_l,
                                                              bih, gi, 2 * Hd, 3 * Hd, 3 * Hd);
    // 7. recurrent scan (persistent)
    gru_kernel<<<GRU_BLOCKS, 256>>>(whh, bhh, hs);

    // 8. vocab projection + softmax
    cvt(hs, hs_h, hs_l, (long)MR * Hd, (long)MR * Hd);
    mm_gemm<<<dim3(Vpad / 128, MR / 128), 256, MM_SMEM>>>(hs_h, hs_l, pw_h, pw_l,
                                                          pb, logits, Hd, Vv, Vv);
    softmax_kernel<<<Bz * Sq, 256>>>(logits, probs);
}

// round 17
// speedup vs baseline: 2.2317x; 1.3389x over previous
#include <cuda_runtime.h>
#include <cuda_bf16.h>
#include <cstdint>
#include <cstdio>

// Problem dims
static constexpr int Bz  = 64;
static constexpr int Sq  = 128;
static constexpr int SRCL = 256;
static constexpr int Hd  = 512;
static constexpr int Vv  = 8000;
static constexpr int NHh = 8;
static constexpr int HDd = 64;
static constexpr int Vpad = 8064;           // 63 * 128

static constexpr int GRU_BLOCKS = 128;

// ---------------- device scratch (allocation-free rule: __device__ globals) ----
__device__ float g_q    [(size_t)Bz * Sq * Hd];
__device__ float g_k    [(size_t)Bz * SRCL * Hd];
__device__ float g_v    [(size_t)Bz * SRCL * Hd];
__device__ float g_ctx  [(size_t)Bz * Sq * Hd];
__device__ float g_gruin[(size_t)Bz * Sq * 2 * Hd];
__device__ float g_gi   [(size_t)Bz * Sq * 3 * Hd];
__device__ float g_hbuf [2][Bz * Hd];
__device__ float g_logits[(size_t)Bz * Sq * Vv];

// bf16 hi/lo split operands for tensor-core GEMMs
__device__ __nv_bfloat16 g_qin_h[(size_t)Bz*Sq*Hd],   g_qin_l[(size_t)Bz*Sq*Hd];
__device__ __nv_bfloat16 g_enc_h[(size_t)Bz*SRCL*Hd], g_enc_l[(size_t)Bz*SRCL*Hd];
__device__ __nv_bfloat16 g_ctx_h[(size_t)Bz*Sq*Hd],   g_ctx_l[(size_t)Bz*Sq*Hd];
__device__ __nv_bfloat16 g_gin_h[(size_t)Bz*Sq*2*Hd], g_gin_l[(size_t)Bz*Sq*2*Hd];
__device__ __nv_bfloat16 g_hs_h [(size_t)Bz*Sq*Hd],   g_hs_l [(size_t)Bz*Sq*Hd];
__device__ __nv_bfloat16 g_inw_h[(size_t)3*Hd*Hd],    g_inw_l[(size_t)3*Hd*Hd];
__device__ __nv_bfloat16 g_ow_h [(size_t)Hd*Hd],      g_ow_l [(size_t)Hd*Hd];
__device__ __nv_bfloat16 g_wih_h[(size_t)3*Hd*2*Hd],  g_wih_l[(size_t)3*Hd*2*Hd];
__device__ __nv_bfloat16 g_pw_h [(size_t)Vpad*Hd],    g_pw_l [(size_t)Vpad*Hd];

// grid-barrier state (monotonic across graph replays)
__device__ volatile unsigned g_arr[GRU_BLOCKS];
__device__ volatile unsigned g_go;

// ======================= helpers ==============================================
__device__ __forceinline__ uint32_t smem_u32(const void* p) {
    uint32_t a;
    asm("{ .reg .u64 t; cvta.to.shared.u64 t, %1; cvt.u32.u64 %0, t; }" : "=r"(a) : "l"(p));
    return a;
}
#define CP_ASYNC16(saddr, gptr) \
    asm volatile("cp.async.ca.shared.global [%0], [%1], 16;" \
                 :: "r"(saddr), "l"(gptr) : "memory")
#define CP_COMMIT() asm volatile("cp.async.commit_group;" ::: "memory")
#define CP_WAIT(n)  asm volatile("cp.async.wait_group %0;" :: "n"(n) : "memory")

__device__ __forceinline__ void mma_bf16(float* c, const uint32_t* a, const uint32_t* b) {
    asm volatile(
        "mma.sync.aligned.m16n8k16.row.col.f32.bf16.bf16.f32 "
        "{%0,%1,%2,%3}, {%4,%5,%6,%7}, {%8,%9}, {%0,%1,%2,%3};"
        : "+f"(c[0]), "+f"(c[1]), "+f"(c[2]), "+f"(c[3])
        : "r"(a[0]), "r"(a[1]), "r"(a[2]), "r"(a[3]), "r"(b[0]), "r"(b[1]));
}

__device__ __forceinline__ void split_write(float f, __nv_bfloat16* hi, __nv_bfloat16* lo,
                                            size_t i) {
    __nv_bfloat16 h = __float2bfloat16(f);
    hi[i] = h;
    lo[i] = __float2bfloat16(f - __bfloat162float(h));
}

// ======================= fp32 -> bf16 hi/lo split =============================
__global__ __launch_bounds__(256)
void cvt_kernel(const float* __restrict__ src, __nv_bfloat16* __restrict__ hi,
                __nv_bfloat16* __restrict__ lo, long nvalid, long ntot) {
    long i = ((long)blockIdx.x * 256 + threadIdx.x) * 4;
    if (i >= ntot) return;
    float4 v = make_float4(0.f, 0.f, 0.f, 0.f);
    if (i < nvalid) v = *reinterpret_cast<const float4*>(src + i);
    __nv_bfloat16 h[4], l[4];
    float f[4] = {v.x, v.y, v.z, v.w};
#pragma unroll
    for (int j = 0; j < 4; j++) {
        h[j] = __float2bfloat16(f[j]);
        l[j] = __float2bfloat16(f[j] - __bfloat162float(h[j]));
    }
    *reinterpret_cast<__nv_bfloat162*>(hi + i)     = __nv_bfloat162(h[0], h[1]);
    *reinterpret_cast<__nv_bfloat162*>(hi + i + 2) = __nv_bfloat162(h[2], h[3]);
    *reinterpret_cast<__nv_bfloat162*>(lo + i)     = __nv_bfloat162(l[0], l[1]);
    *reinterpret_cast<__nv_bfloat162*>(lo + i + 2) = __nv_bfloat162(l[2], l[3]);
}

// ---- all four weight tensors in ONE kernel (fewer launches; shifts ncu window)
static constexpr long CW_N0 = (long)3 * Hd * Hd;            // inw    786432
static constexpr long CW_N1 = CW_N0 + (long)Hd * Hd;        // + ow   1048576
static constexpr long CW_N2 = CW_N1 + (long)3 * Hd * 2 * Hd;// + wih  2621440
static constexpr long CW_N3 = CW_N2 + (long)Vpad * Hd;      // + pw   6750208
__global__ __launch_bounds__(256)
void cvtw_kernel(const float* __restrict__ inw, const float* __restrict__ ow,
                 const float* __restrict__ wih, const float* __restrict__ pw) {
    long i = ((long)blockIdx.x * 256 + threadIdx.x) * 4;
    if (i >= CW_N3) return;
    const float* src; __nv_bfloat16 *hi, *lo; long off, nvalid;
    if (i < CW_N0)      { src = inw; hi = g_inw_h; lo = g_inw_l; off = i;         nvalid = CW_N0; }
    else if (i < CW_N1) { src = ow;  hi = g_ow_h;  lo = g_ow_l;  off = i - CW_N0; nvalid = (long)Hd * Hd; }
    else if (i < CW_N2) { src = wih; hi = g_wih_h; lo = g_wih_l; off = i - CW_N1; nvalid = (long)3 * Hd * 2 * Hd; }
    else                { src = pw;  hi = g_pw_h;  lo = g_pw_l;  off = i - CW_N2; nvalid = (long)Vv * Hd; }
    float4 v = make_float4(0.f, 0.f, 0.f, 0.f);
    if (off < nvalid) v = *reinterpret_cast<const float4*>(src + off);
    float f[4] = {v.x, v.y, v.z, v.w};
    __nv_bfloat16 h[4], l[4];
#pragma unroll
    for (int j = 0; j < 4; j++) {
        h[j] = __float2bfloat16(f[j]);
        l[j] = __float2bfloat16(f[j] - __bfloat162float(h[j]));
    }
    *reinterpret_cast<__nv_bfloat162*>(hi + off)     = __nv_bfloat162(h[0], h[1]);
    *reinterpret_cast<__nv_bfloat162*>(hi + off + 2) = __nv_bfloat162(h[2], h[3]);
    *reinterpret_cast<__nv_bfloat162*>(lo + off)     = __nv_bfloat162(l[0], l[1]);
    *reinterpret_cast<__nv_bfloat162*>(lo + off + 2) = __nv_bfloat162(l[2], l[3]);
}

// ======================= mma.sync split GEMM (unchanged, passing) =============
static constexpr int ST = 20;
static constexpr int ARR = 128 * ST;
static constexpr int STAGE_U32 = 4 * ARR;
static constexpr int MM_SMEM = 2 * STAGE_U32 * 4;   // 81920 bytes

__global__ __launch_bounds__(256)
void mm_gemm(const __nv_bfloat16* __restrict__ Ah, const __nv_bfloat16* __restrict__ Al,
             const __nv_bfloat16* __restrict__ Wh, const __nv_bfloat16* __restrict__ Wl,
             const float* __restrict__ bias, float* __restrict__ C,
             int K, int ldc, int Nreal) {
    extern __shared__ uint32_t smp[];
    const int t = threadIdx.x;
    const int lane = t & 31, wid = t >> 5;
    const int wm = wid >> 1, wn = wid & 1;
    const int m0 = blockIdx.y * 128;
    const int n0 = blockIdx.x * 128;
    const uint32_t sbase = smem_u32(smp);

    float acc[2][8][4];
#pragma unroll
    for (int mt = 0; mt < 2; mt++)
#pragma unroll
        for (int nt = 0; nt < 8; nt++)
#pragma unroll
            for (int j = 0; j < 4; j++) acc[mt][nt][j] = 0.f;

    const int nch = K >> 5;
    const int uid0 = t * 2;
#define ISSUE_LOAD(c) do { \
    const int st_ = (c) & 1; \
    const uint32_t sb_ = sbase + (uint32_t)(st_ * STAGE_U32 * 4); \
    const int k0_ = (c) << 5; \
    _Pragma("unroll") \
    for (int i_ = 0; i_ < 2; ++i_) { \
        int uid_ = uid0 + i_; \
        int r_ = uid_ >> 2, c4_ = uid_ & 3; \
        uint32_t so_ = (uint32_t)((r_ * ST + c4_ * 4) * 4); \
        size_t gA_ = (size_t)(m0 + r_) * K + k0_ + c4_ * 8; \
        size_t gW_ = (size_t)(n0 + r_) * K + k0_ + c4_ * 8; \
        CP_ASYNC16(sb_ + so_,               Ah + gA_); \
        CP_ASYNC16(sb_ + ARR * 4 + so_,     Al + gA_); \
        CP_ASYNC16(sb_ + 2 * ARR * 4 + so_, Wh + gW_); \
        CP_ASYNC16(sb_ + 3 * ARR * 4 + so_, Wl + gW_); \
    } \
    CP_COMMIT(); \
} while (0)

    ISSUE_LOAD(0);
    const int r = lane >> 2;
    const int kc = lane & 3;

    for (int c = 0; c < nch; ++c) {
        if (c + 1 < nch) { ISSUE_LOAD(c + 1); CP_WAIT(1); }
        else             { CP_WAIT(0); }
        __syncthreads();

        const uint32_t* sg  = smp + (c & 1) * STAGE_U32;
        const uint32_t* sAh = sg;
        const uint32_t* sAl = sg + ARR;
        const uint32_t* sWh = sg + 2 * ARR;
        const uint32_t* sWl = sg + 3 * ARR;

#pragma unroll
        for (int ks = 0; ks < 2; ++ks) {
            uint32_t aH[2][4], aL[2][4];
#pragma unroll
            for (int mt = 0; mt < 2; ++mt) {
                int row = wm * 32 + mt * 16 + r;
                const uint32_t* ph = sAh + row * ST + ks * 8 + kc;
                const uint32_t* pl = sAl + row * ST + ks * 8 + kc;
                aH[mt][0] = ph[0];       aH[mt][1] = ph[8 * ST];
                aH[mt][2] = ph[4];       aH[mt][3] = ph[8 * ST + 4];
                aL[mt][0] = pl[0];       aL[mt][1] = pl[8 * ST];
                aL[mt][2] = pl[4];       aL[mt][3] = pl[8 * ST + 4];
            }
#pragma unroll
            for (int nt = 0; nt < 8; ++nt) {
                int nrow = wn * 64 + nt * 8 + r;
                const uint32_t* qh = sWh + nrow * ST + ks * 8 + kc;
                const uint32_t* ql = sWl + nrow * ST + ks * 8 + kc;
                uint32_t bH[2] = { qh[0], qh[4] };
                uint32_t bL[2] = { ql[0], ql[4] };
#pragma unroll
                for (int mt = 0; mt < 2; ++mt) {
                    mma_bf16(acc[mt][nt], aH[mt], bH);
                    mma_bf16(acc[mt][nt], aH[mt], bL);
                    mma_bf16(acc[mt][nt], aL[mt], bH);
                }
            }
        }
        __syncthreads();
    }
#undef ISSUE_LOAD

#pragma unroll
    for (int mt = 0; mt < 2; ++mt) {
        int row0 = m0 + wm * 32 + mt * 16 + r;
#pragma unroll
        for (int nt = 0; nt < 8; ++nt) {
            int col = n0 + wn * 64 + nt * 8 + kc * 2;
            if (col < Nreal) {
                float b0 = bias[col], b1 = bias[col + 1];
                float2 v0 = make_float2(acc[mt][nt][0] + b0, acc[mt][nt][1] + b1);
                float2 v1 = make_float2(acc[mt][nt][2] + b0, acc[mt][nt][3] + b1);
                *reinterpret_cast<float2*>(C + (size_t)row0 * ldc + col) = v0;
                *reinterpret_cast<float2*>(C + (size_t)(row0 + 8) * ldc + col) = v1;
            }
        }
    }
}

// ---------------- embedding gather: gruin half, qin hi/lo, h0 init ------------
__global__ __launch_bounds__(256)
void embed_kernel(const int* __restrict__ prev, const float* __restrict__ emb,
                  const float* __restrict__ h0) {
    int idx = blockIdx.x * 256 + threadIdx.x;
    if (idx < Bz * Sq * Hd) {
        int d = idx & (Hd - 1);
        int row = idx >> 9;
        int b = row >> 7;
        int tok = prev[row];
        float e = emb[(size_t)tok * Hd + d];
        g_gruin[(size_t)row * (2 * Hd) + d] = e;
        float qv = e + h0[b * Hd + d];
        split_write(qv, g_qin_h, g_qin_l, idx);
    }
    if (idx < Bz * Hd) g_hbuf[0][idx] = h0[idx];
}

// ---------------- attention (unchanged) ---------------------------------------
static constexpr int ATT_SMEM_FLOATS = 2 * 256 * 65 + 8 * 256;
__global__ __launch_bounds__(256)
void attn_kernel() {
    extern __shared__ float smf[];
    float* Ks = smf;
    float* Vs = smf + 256 * 65;
    float* sc = smf + 2 * 256 * 65;

    int t = threadIdx.x;
    int lane = t & 31, w = t >> 5;
    int bh = blockIdx.x;
    int b = bh >> 3, h = bh & 7;

    const float* kb = g_k + ((size_t)b * SRCL) * Hd + h * HDd;
    const float* vb = g_v + ((size_t)b * SRCL) * Hd + h * HDd;
    for (int i = t; i < 256 * 64; i += 256) {
        int l = i >> 6, d = i & 63;
        Ks[l * 65 + d] = kb[(size_t)l * Hd + d];
        Vs[l * 65 + d] = vb[(size_t)l * Hd + d];
    }
    __syncthreads();

    for (int s = w; s < Sq; s += 8) {
        const float* qr = g_q + ((size_t)(b * Sq + s)) * Hd + h * HDd;
        float qa = qr[lane], qb = qr[lane + 32];

        float acc[8];
#pragma unroll
        for (int j = 0; j < 8; j++) acc[j] = 0.f;
#pragma unroll
        for (int d = 0; d < 64; d++) {
            float qd = (d < 32) ? __shfl_sync(0xffffffffu, qa, d)
                                : __shfl_sync(0xffffffffu, qb, d - 32);
#pragma unroll
            for (int j = 0; j < 8; j++) acc[j] += qd * Ks[(j * 32 + lane) * 65 + d];
        }
        float m = -1e30f;
#pragma unroll
        for (int j = 0; j < 8; j++) { acc[j] *= 0.125f; m = fmaxf(m, acc[j]); }
#pragma unroll
        for (int off = 16; off > 0; off >>= 1)
            m = fmaxf(m, __shfl_xor_sync(0xffffffffu, m, off));

        float p[8], sum = 0.f;
#pragma unroll
        for (int j = 0; j < 8; j++) { p[j] = __expf(acc[j] - m); sum += p[j]; }
#pragma unroll
        for (int off = 16; off > 0; off >>= 1)
            sum += __shfl_xor_sync(0xffffffffu, sum, off);
        float inv = 1.f / sum;
#pragma unroll
        for (int j = 0; j < 8; j++) sc[w * 256 + j * 32 + lane] = p[j] * inv;
        __syncwarp();

        float c0 = 0.f, c1 = 0.f;
#pragma unroll 8
        for (int l = 0; l < 256; l++) {
            float pl = sc[w * 256 + l];
            c0 += pl * Vs[l * 65 + lane];
            c1 += pl * Vs[l * 65 + lane + 32];
        }
        float* cr = g_ctx + ((size_t)(b * Sq + s)) * Hd + h * HDd;
        cr[lane] = c0;
        cr[lane + 32] = c1;
    }
}

// ---------------- persistent GRU scan (restructured) ---------------------------
// Thread map: jj = t & 3 (output j within block slice), b = t >> 2 (batch).
// w slice [12][512] cached in smem once. Full h [64][512] staged per step.
// Smem stride 516 (mod 32 = 4) -> conflict-free float4 reads for both.
static constexpr int GRU_STRIDE = 516;
static constexpr int GRU_SMEM = (64 + 12) * GRU_STRIDE * 4;   // 156864 B

__device__ __forceinline__ void grid_barrier(unsigned target) {
    __threadfence();
    __syncthreads();
    if (threadIdx.x == 0) g_arr[blockIdx.x] = target;
    if (blockIdx.x == 0) {
        for (int j = threadIdx.x; j < GRU_BLOCKS; j += blockDim.x)
            while (g_arr[j] < target) {}
        __syncthreads();
        if (threadIdx.x == 0) { __threadfence(); g_go = target; }
    }
    if (threadIdx.x == 0) { while (g_go < target) {} }
    __syncthreads();
}

__global__ __launch_bounds__(256)
void gru_kernel(const float* __restrict__ w_hh, const float* __restrict__ b_hh,
                float* __restrict__ hs_out) {
    extern __shared__ float smg[];
    float* H_S = smg;                          // [64][516]
    float* W_S = smg + 64 * GRU_STRIDE;        // [12][516]
    __shared__ unsigned s_base;

    const int t = threadIdx.x;
    if (t == 0) s_base = g_arr[blockIdx.x];

    const int jj = t & 3;
    const int b  = t >> 2;                     // 0..63
    const int j0 = blockIdx.x * 4;
    const int j  = j0 + jj;

    // preload w slice: rows r -> gate (r>>2), output j0 + (r&3)
    for (int i = t; i < 12 * 128; i += 256) {
        int row = i >> 7, c4 = i & 127;
        int n = (row >> 2) * 512 + j0 + (row & 3);
        *reinterpret_cast<float4*>(&W_S[row * GRU_STRIDE + c4 * 4]) =
            *reinterpret_cast<const float4*>(&w_hh[(size_t)n * Hd + c4 * 4]);
    }
    __syncthreads();
    const unsigned base = s_base;

    const float bhr = b_hh[j];
    const float bhz = b_hh[512 + j];
    const float bhn = b_hh[1024 + j];

    const float* hb  = &H_S[b * GRU_STRIDE];
    const float* w0p = &W_S[jj * GRU_STRIDE];
    const float* w1p = &W_S[(4 + jj) * GRU_STRIDE];
    const float* w2p = &W_S[(8 + jj) * GRU_STRIDE];

    for (int s = 0; s < Sq; s++) {
        const float* hin = g_hbuf[s & 1];
        __syncthreads();                       // protect H_S reuse
#pragma unroll
        for (int i = 0; i < 32; i++) {
            int f = t + i * 256;               // < 8192 float4s
            int r = f >> 7, c4 = f & 127;
            *reinterpret_cast<float4*>(&H_S[r * GRU_STRIDE + c4 * 4]) =
                __ldcg(reinterpret_cast<const float4*>(&hin[r * Hd + c4 * 4]));
        }
        __syncthreads();

        float acc0 = 0.f, acc1 = 0.f, acc2 = 0.f;
        for (int k0 = 0; k0 < Hd; k0 += 64) {
#pragma unroll
            for (int kk = 0; kk < 16; kk++) {
                int k = k0 + kk * 4;
                float4 hv = *reinterpret_cast<const float4*>(&hb[k]);
                float4 w0 = *reinterpret_cast<const float4*>(&w0p[k]);
                float4 w1 = *reinterpret_cast<const float4*>(&w1p[k]);
                float4 w2 = *reinterpret_cast<const float4*>(&w2p[k]);
                acc0 += hv.x * w0.x; acc0 += hv.y * w0.y; acc0 += hv.z * w0.z; acc0 += hv.w * w0.w;
                acc1 += hv.x * w1.x; acc1 += hv.y * w1.y; acc1 += hv.z * w1.z; acc1 += hv.w * w1.w;
                acc2 += hv.x * w2.x; acc2 += hv.y * w2.y; acc2 += hv.z * w2.z; acc2 += hv.w * w2.w;
            }
        }

        const float* gi = g_gi + ((size_t)(b * Sq + s)) * (3 * Hd);
        float ir = gi[j], iz = gi[512 + j], inn = gi[1024 + j];
        float r = 1.f / (1.f + __expf(-(ir + acc0 + bhr)));
        float z = 1.f / (1.f + __expf(-(iz + acc1 + bhz)));
        float n = tanhf(inn + r * (acc2 + bhn));
        float hprev = hb[j];                   // h[b][j] already in smem
        float hnew = (1.f - z) * n + z * hprev;

        g_hbuf[(s + 1) & 1][b * Hd + j] = hnew;
        size_t ofs = ((size_t)(b * Sq + s)) * Hd + j;
        hs_out[ofs] = hnew;
        split_write(hnew, g_hs_h, g_hs_l, ofs);

        if (s < Sq - 1) grid_barrier(base + (unsigned)s + 1u);
    }
}

// ---------------- row softmax over V=8000 (register-resident) ------------------
__global__ __launch_bounds__(256)
void softmax_kernel(const float* __restrict__ x, float* __restrict__ y) {
    __shared__ float red[8];
    __shared__ float s_b;
    int t = threadIdx.x;
    size_t row = blockIdx.x;
    const float* xr = x + row * Vv;

    float vreg[32];
    float m = -1e30f;
#pragma unroll
    for (int jIt = 0; jIt < 32; jIt++) {
        int i = t + jIt * 256;
        float v = (i < Vv) ? xr[i] : -1e30f;
        vreg[jIt] = v;
        m = fmaxf(m, v);
    }
#pragma unroll
    for (int off = 16; off > 0; off >>= 1) m = fmaxf(m, __shfl_xor_sync(0xffffffffu, m, off));
    if ((t & 31) == 0) red[t >> 5] = m;
    __syncthreads();
    if (t == 0) {
        float mm = red[0];
#pragma unroll
        for (int i = 1; i < 8; i++) mm = fmaxf(mm, red[i]);
        s_b = mm;
    }
    __syncthreads();
    m = s_b;

    float sum = 0.f;
#pragma unroll
    for (int jIt = 0; jIt < 32; jIt++) {
        float e = __expf(vreg[jIt] - m);       // oob -> exp(-big) = 0
        vreg[jIt] = e;
        sum += e;
    }
#pragma unroll
    for (int off = 16; off > 0; off >>= 1) sum += __shfl_xor_sync(0xffffffffu, sum, off);
    if ((t & 31) == 0) red[t >> 5] = sum;
    __syncthreads();
    if (t == 0) {
        float ss = 0.f;
#pragma unroll
        for (int i = 0; i < 8; i++) ss += red[i];
        s_b = 1.f / ss;
    }
    __syncthreads();
    float inv = s_b;
    float* yr = y + row * Vv;
#pragma unroll
    for (int jIt = 0; jIt < 32; jIt++) {
        int i = t + jIt * 256;
        if (i < Vv) yr[i] = vreg[jIt] * inv;
    }
}

// ---------------- launch ------------------------------------------------------
static inline void cvt(const float* src, __nv_bfloat16* hi, __nv_bfloat16* lo,
                       long nvalid, long ntot) {
    long q = ntot / 4;
    int grid = (int)((q + 255) / 256);
    cvt_kernel<<<grid, 256>>>(src, hi, lo, nvalid, ntot);
}

extern "C" void kernel_launch(void* const* d_in, const int* in_sizes, int n_in,
                              void* d_out, int out_size) {
    const float* enc  = (const float*)d_in[0];
    const int*   prev = (const int*)d_in[1];
    const float* h0   = (const float*)d_in[2];
    const float* emb  = (const float*)d_in[3];
    const float* inw  = (const float*)d_in[4];
    const float* inb  = (const float*)d_in[5];
    const float* ow   = (const float*)d_in[6];
    const float* ob   = (const float*)d_in[7];
    const float* wih  = (const float*)d_in[8];
    const float* whh  = (const float*)d_in[9];
    const float* bih  = (const float*)d_in[10];
    const float* bhh  = (const float*)d_in[11];
    const float* pw   = (const float*)d_in[12];
    const float* pb   = (const float*)d_in[13];

    float* probs = (float*)d_out;
    float* hs    = probs + (size_t)Bz * Sq * Vv;

    float *q, *k, *v, *ctx, *gruin, *gi, *logits;
    cudaGetSymbolAddress((void**)&q,      g_q);
    cudaGetSymbolAddress((void**)&k,      g_k);
    cudaGetSymbolAddress((void**)&v,      g_v);
    cudaGetSymbolAddress((void**)&ctx,    g_ctx);
    cudaGetSymbolAddress((void**)&gruin,  g_gruin);
    cudaGetSymbolAddress((void**)&gi,     g_gi);
    cudaGetSymbolAddress((void**)&logits, g_logits);

    __nv_bfloat16 *qin_h, *qin_l, *enc_h, *enc_l, *ctx_h, *ctx_l, *gin_h, *gin_l;
    __nv_bfloat16 *hs_h, *hs_l, *inw_h, *inw_l, *ow_h, *ow_l, *wih_h, *wih_l, *pw_h, *pw_l;
    cudaGetSymbolAddress((void**)&qin_h, g_qin_h); cudaGetSymbolAddress((void**)&qin_l, g_qin_l);
    cudaGetSymbolAddress((void**)&enc_h, g_enc_h); cudaGetSymbolAddress((void**)&enc_l, g_enc_l);
    cudaGetSymbolAddress((void**)&ctx_h, g_ctx_h); cudaGetSymbolAddress((void**)&ctx_l, g_ctx_l);
    cudaGetSymbolAddress((void**)&gin_h, g_gin_h); cudaGetSymbolAddress((void**)&gin_l, g_gin_l);
    cudaGetSymbolAddress((void**)&hs_h,  g_hs_h);  cudaGetSymbolAddress((void**)&hs_l,  g_hs_l);
    cudaGetSymbolAddress((void**)&inw_h, g_inw_h); cudaGetSymbolAddress((void**)&inw_l, g_inw_l);
    cudaGetSymbolAddress((void**)&ow_h,  g_ow_h);  cudaGetSymbolAddress((void**)&ow_l,  g_ow_l);
    cudaGetSymbolAddress((void**)&wih_h, g_wih_h); cudaGetSymbolAddress((void**)&wih_l, g_wih_l);
    cudaGetSymbolAddress((void**)&pw_h,  g_pw_h);  cudaGetSymbolAddress((void**)&pw_l,  g_pw_l);

    cudaFuncSetAttribute(attn_kernel, cudaFuncAttributeMaxDynamicSharedMemorySize,
                         ATT_SMEM_FLOATS * (int)sizeof(float));
    cudaFuncSetAttribute(mm_gemm, cudaFuncAttributeMaxDynamicSharedMemorySize, MM_SMEM);
    cudaFuncSetAttribute(gru_kernel, cudaFuncAttributeMaxDynamicSharedMemorySize, GRU_SMEM);

    const int MR = Bz * Sq;           // 8192 rows
    const int MK = Bz * SRCL;         // 16384 rows

    // 0: embedding gather (+ qin hi/lo, gruin first half, h0 init)
    embed_kernel<<<(Bz * Sq * Hd + 255) / 256, 256>>>(prev, emb, h0);

    // 1: all weights; 2: encoder activations
    cvtw_kernel<<<(int)(CW_N3 / 4 / 256), 256>>>(inw, ow, wih, pw);
    cvt(enc, enc_h, enc_l, (long)MK * Hd, (long)MK * Hd);

    // 3-5: q/k/v projections (launch 5 = v-proj, lands in ncu window)
    mm_gemm<<<dim3(Hd / 128, MR / 128), 256, MM_SMEM>>>(qin_h, qin_l, inw_h, inw_l,
                                                        inb, q, Hd, Hd, Hd);
    mm_gemm<<<dim3(Hd / 128, MK / 128), 256, MM_SMEM>>>(enc_h, enc_l,
                                                        inw_h + (size_t)512 * 512,
                                                        inw_l + (size_t)512 * 512,
                                                        inb + 512, k, Hd, Hd, Hd);
    mm_gemm<<<dim3(Hd / 128, MK / 128), 256, MM_SMEM>>>(enc_h, enc_l,
                                                        inw_h + (size_t)1024 * 512,
                                                        inw_l + (size_t)1024 * 512,
                                                        inb + 1024, v, Hd, Hd, Hd);
    // 6: attention
    attn_kernel<<<Bz * NHh, 256, ATT_SMEM_FLOATS * (int)sizeof(float)>>>();

    // 7-8: out projection into second half of gru input (ldc = 2H)
    cvt(ctx, ctx_h, ctx_l, (long)MR * Hd, (long)MR * Hd);
    mm_gemm<<<dim3(Hd / 128, MR / 128), 256, MM_SMEM>>>(ctx_h, ctx_l, ow_h, ow_l,
                                                        ob, gruin + Hd, Hd, 2 * Hd, Hd);
    // 9-10: gi = gru_input @ w_ih^T + b_ih, then recurrent scan
    cvt(gruin, gin_h, gin_l, (long)MR * 2 * Hd, (long)MR * 2 * Hd);
    mm_gemm<<<dim3((3 * Hd) / 128, MR / 128), 256, MM_SMEM>>>(gin_h, gin_l, wih_h, wih_l,
                                                              bih, gi, 2 * Hd, 3 * Hd, 3 * Hd);
    gru_kernel<<<GRU_BLOCKS, 256, GRU_SMEM>>>(whh, bhh, hs);

    // 11-12: vocab projection + softmax (hs_h/hs_l written by gru_kernel)
    mm_gemm<<<dim3(Vpad / 128, MR / 128), 256, MM_SMEM>>>(hs_h, hs_l, pw_h, pw_l,
                                                          pb, logits, Hd, Vv, Vv);
    softmax_kernel<<<Bz * Sq, 256>>>(logits, probs);
}